// round 1
// baseline (speedup 1.0000x reference)
#include <cuda_runtime.h>
#include <mma.h>
#include <cstdint>

using namespace nvcuda;

#define D_MODEL   1024
#define D_STATE   128
#define D_INNER   2048
#define NHEADS    32
#define HEADDIM   64
#define CONV_DIM  2304
#define D_IN_PROJ 4384
#define SEQLEN    2048
#define BATCH     2
#define BL        (BATCH * SEQLEN)   // 4096

// ---------------- device scratch (no allocations allowed) ----------------
__device__ float g_zx[(size_t)BL * D_IN_PROJ];    // in_proj output  [4096, 4384]
__device__ float g_xconv[(size_t)BL * CONV_DIM];  // conv+silu out   [4096, 2304]
__device__ float g_dtp[(size_t)BL * NHEADS];      // softplus(dt+bias)
__device__ float g_dA[(size_t)BL * NHEADS];       // exp(dt*A)
__device__ float g_y[(size_t)BL * D_INNER];       // scan output + D*x
__device__ float g_nrm[(size_t)BL * D_INNER];     // gated + rmsnormed

// =====================================================================
// GEMM: C[M,N] = A[M,K] (row-major) * B[N,K]^T (row-major), optional +resid
// tf32 WMMA with 3-term split (AhBh + AlBh + AhBl) for ~fp32 accuracy.
// =====================================================================
#define BMT 128
#define BNT 128
#define BKT 32
#define LDT (BKT + 4)

__global__ __launch_bounds__(256) void gemm_tf32_split(
    const float* __restrict__ A, const float* __restrict__ B,
    float* __restrict__ C, const float* __restrict__ resid,
    int M, int N, int K)
{
    __shared__ float As[BMT][LDT];
    __shared__ float Bs[BNT][LDT];
    const int bm  = blockIdx.y * BMT;
    const int bn  = blockIdx.x * BNT;
    const int tid = threadIdx.x;
    const int wid = tid >> 5;
    const int wm  = (wid & 3) * 32;   // 4 warps along M (32 rows each)
    const int wn  = (wid >> 2) * 64;  // 2 warps along N (64 cols each)

    wmma::fragment<wmma::accumulator, 16, 16, 8, float> acc[2][4];
#pragma unroll
    for (int i = 0; i < 2; i++)
#pragma unroll
        for (int j = 0; j < 4; j++) wmma::fill_fragment(acc[i][j], 0.0f);

    for (int k0 = 0; k0 < K; k0 += BKT) {
        // load A tile 128x32 (always in-bounds: M % 128 == 0, K % 32 == 0)
#pragma unroll
        for (int i = 0; i < 4; i++) {
            int f4 = tid + i * 256;
            int r  = f4 >> 3;
            int c  = (f4 & 7) << 2;
            float4 v = *(const float4*)(A + (size_t)(bm + r) * K + k0 + c);
            *(float4*)&As[r][c] = v;
        }
        // load B tile 128x32 with N-guard (zero fill)
#pragma unroll
        for (int i = 0; i < 4; i++) {
            int f4 = tid + i * 256;
            int r  = f4 >> 3;
            int c  = (f4 & 7) << 2;
            float4 v = make_float4(0.f, 0.f, 0.f, 0.f);
            if (bn + r < N) v = *(const float4*)(B + (size_t)(bn + r) * K + k0 + c);
            *(float4*)&Bs[r][c] = v;
        }
        __syncthreads();

#pragma unroll
        for (int kk = 0; kk < BKT; kk += 8) {
            wmma::fragment<wmma::matrix_a, 16, 16, 8, wmma::precision::tf32, wmma::row_major> ah[2], al[2];
            wmma::fragment<wmma::matrix_b, 16, 16, 8, wmma::precision::tf32, wmma::col_major> bh[4], bl[4];
#pragma unroll
            for (int i = 0; i < 2; i++) {
                wmma::load_matrix_sync(ah[i], &As[wm + i * 16][kk], LDT);
#pragma unroll
                for (int e = 0; e < ah[i].num_elements; e++) {
                    float f = ah[i].x[e];
                    float h = wmma::__float_to_tf32(f);
                    al[i].x[e] = wmma::__float_to_tf32(f - h);
                    ah[i].x[e] = h;
                }
            }
#pragma unroll
            for (int j = 0; j < 4; j++) {
                wmma::load_matrix_sync(bh[j], &Bs[wn + j * 16][kk], LDT);
#pragma unroll
                for (int e = 0; e < bh[j].num_elements; e++) {
                    float f = bh[j].x[e];
                    float h = wmma::__float_to_tf32(f);
                    bl[j].x[e] = wmma::__float_to_tf32(f - h);
                    bh[j].x[e] = h;
                }
            }
#pragma unroll
            for (int i = 0; i < 2; i++)
#pragma unroll
                for (int j = 0; j < 4; j++) {
                    wmma::mma_sync(acc[i][j], ah[i], bh[j], acc[i][j]);
                    wmma::mma_sync(acc[i][j], al[i], bh[j], acc[i][j]);
                    wmma::mma_sync(acc[i][j], ah[i], bl[j], acc[i][j]);
                }
        }
        __syncthreads();
    }

#pragma unroll
    for (int i = 0; i < 2; i++)
#pragma unroll
        for (int j = 0; j < 4; j++) {
            int row = bm + wm + i * 16;
            int col = bn + wn + j * 16;
            if (col < N) {
                if (resid != nullptr) {
                    wmma::fragment<wmma::accumulator, 16, 16, 8, float> r;
                    wmma::load_matrix_sync(r, resid + (size_t)row * N + col, N, wmma::mem_row_major);
#pragma unroll
                    for (int e = 0; e < r.num_elements; e++) acc[i][j].x[e] += r.x[e];
                }
                wmma::store_matrix_sync(C + (size_t)row * N + col, acc[i][j], N, wmma::mem_row_major);
            }
        }
}

// =====================================================================
// Causal depthwise conv (width 4) + bias + SiLU over zx cols [2048,4352)
// =====================================================================
__global__ __launch_bounds__(256) void conv_silu_kernel(
    const float* __restrict__ cw, const float* __restrict__ cb)
{
    int c   = blockIdx.x * 256 + threadIdx.x;   // 0..2303
    int row = blockIdx.y;                       // 0..4095
    int t   = row & (SEQLEN - 1);
    float4 w = *(const float4*)(cw + c * 4);
    const float* wv = (const float*)&w;
    const float* col = g_zx + (size_t)row * D_IN_PROJ + D_INNER + c;
    float s = 0.f;
#pragma unroll
    for (int j = 0; j < 4; j++) {
        int tt = t - 3 + j;
        if (tt >= 0) s = fmaf(wv[j], col[(j - 3) * D_IN_PROJ], s);
    }
    s += cb[c];
    g_xconv[(size_t)row * CONV_DIM + c] = s / (1.f + expf(-s));
}

// =====================================================================
// dt preprocessing: dtp = softplus(dt + bias), dA = exp(-exp(A_log)*dtp)
// =====================================================================
__global__ __launch_bounds__(256) void dt_kernel(
    const float* __restrict__ dt_bias, const float* __restrict__ A_log)
{
    int idx = blockIdx.x * 256 + threadIdx.x;   // BL*32
    int row = idx >> 5;
    int hh  = idx & 31;
    float v  = g_zx[(size_t)row * D_IN_PROJ + (D_INNER + CONV_DIM) + hh] + dt_bias[hh];
    float sp = (v > 20.f) ? v : log1pf(expf(v));
    g_dtp[idx] = sp;
    g_dA[idx]  = expf(-expf(A_log[hh]) * sp);
}

// =====================================================================
// Sequential selective scan: one block per (batch, head).
// 256 threads; thread (p = tid>>2, q = tid&3) owns 16 f32x2 state pairs
// (n = 2*(q*16+jp) .. +1). B/C staged through a 3-deep smem ring with
// distance-2 prefetch, pair-rotated to avoid 4-way bank conflicts.
// =====================================================================
typedef unsigned long long ull;

__device__ __forceinline__ ull f32x2_fma(ull a, ull b, ull c) {
    ull d;
    asm("fma.rn.f32x2 %0, %1, %2, %3;" : "=l"(d) : "l"(a), "l"(b), "l"(c));
    return d;
}
__device__ __forceinline__ ull f32x2_mul(ull a, ull b) {
    ull d;
    asm("mul.rn.f32x2 %0, %1, %2;" : "=l"(d) : "l"(a), "l"(b));
    return d;
}
__device__ __forceinline__ ull f32x2_pack(float x) {
    ull d;
    asm("mov.b64 %0, {%1, %2};" : "=l"(d) : "f"(x), "f"(x));
    return d;
}
__device__ __forceinline__ float f32x2_sum(ull a) {
    float lo, hi;
    asm("mov.b64 {%0, %1}, %2;" : "=f"(lo), "=f"(hi) : "l"(a));
    return lo + hi;
}

__global__ __launch_bounds__(256) void scan_kernel(const float* __restrict__ Dv)
{
    const int bi  = blockIdx.x >> 5;
    const int h   = blockIdx.x & 31;
    const int tid = threadIdx.x;
    const int p   = tid >> 2;
    const int q   = tid & 3;

    __shared__ float  s_xs[3][64];
    __shared__ float2 s_B[3][64];
    __shared__ float2 s_C[3][64];
    __shared__ float  s_sc[3][2];

    ull S[16];
#pragma unroll
    for (int i = 0; i < 16; i++) S[i] = 0ULL;

    const float Dh = Dv[h];
    const float* xcb = g_xconv + (size_t)bi * SEQLEN * CONV_DIM;
    const float* dAb = g_dA  + (size_t)bi * SEQLEN * NHEADS + h;
    const float* dtb = g_dtp + (size_t)bi * SEQLEN * NHEADS + h;

    auto stage = [&](int t, int buf) {
        const float* rowp = xcb + (size_t)t * CONV_DIM;
        if (tid < 32) {
            ((float2*)s_xs[buf])[tid] = ((const float2*)(rowp + h * 64))[tid];
        } else if (tid < 96) {
            int i = tid - 32;
            int dst = (i & 48) | ((i + ((i >> 4) << 2)) & 15);
            s_B[buf][dst] = ((const float2*)(rowp + D_INNER))[i];
        } else if (tid < 160) {
            int i = tid - 96;
            int dst = (i & 48) | ((i + ((i >> 4) << 2)) & 15);
            s_C[buf][dst] = ((const float2*)(rowp + D_INNER + D_STATE))[i];
        } else if (tid == 160) {
            s_sc[buf][0] = dAb[(size_t)t * NHEADS];
        } else if (tid == 161) {
            s_sc[buf][1] = dtb[(size_t)t * NHEADS];
        }
    };

    stage(0, 0);
    stage(1, 1);
    __syncthreads();

    int ofs[16];
#pragma unroll
    for (int jp = 0; jp < 16; jp++) ofs[jp] = (q << 4) | ((jp + (q << 2)) & 15);

    int buf = 0;
    for (int t = 0; t < SEQLEN; t++) {
        if (t + 2 < SEQLEN) {
            int nb = buf + 2; if (nb >= 3) nb -= 3;
            stage(t + 2, nb);
        }
        const float dAv = s_sc[buf][0];
        const float dtv = s_sc[buf][1];
        const float xsv = s_xs[buf][p];
        const ull dA2  = f32x2_pack(dAv);
        const ull xdt2 = f32x2_pack(xsv * dtv);
        const ull* Bb = (const ull*)s_B[buf];
        const ull* Cb = (const ull*)s_C[buf];
        ull y0 = 0ULL, y1 = 0ULL;
#pragma unroll
        for (int jp = 0; jp < 16; jp++) {
            ull bb = Bb[ofs[jp]];
            ull cc = Cb[ofs[jp]];
            ull s  = f32x2_fma(dA2, S[jp], f32x2_mul(xdt2, bb));
            S[jp] = s;
            if (jp & 1) y1 = f32x2_fma(s, cc, y1);
            else        y0 = f32x2_fma(s, cc, y0);
        }
        float yacc = f32x2_sum(y0) + f32x2_sum(y1);
        yacc += __shfl_xor_sync(0xffffffffu, yacc, 1);
        yacc += __shfl_xor_sync(0xffffffffu, yacc, 2);
        if (q == 0) {
            g_y[((size_t)bi * SEQLEN + t) * D_INNER + h * 64 + p] = fmaf(Dh, xsv, yacc);
        }
        buf = (buf == 2) ? 0 : buf + 1;
        __syncthreads();
    }
}

// =====================================================================
// y * silu(z), then RMSNorm with norm_w. One block per row.
// =====================================================================
__global__ __launch_bounds__(256) void gatenorm_kernel(const float* __restrict__ nw)
{
    int row = blockIdx.x;
    int tid = threadIdx.x;
    const float* yr = g_y  + (size_t)row * D_INNER;
    const float* zr = g_zx + (size_t)row * D_IN_PROJ;  // z = cols [0,2048)
    float v[8];
    float ss = 0.f;
#pragma unroll
    for (int i = 0; i < 8; i++) {
        int c = tid + i * 256;
        float z = zr[c];
        float val = yr[c] * (z / (1.f + expf(-z)));
        v[i] = val;
        ss = fmaf(val, val, ss);
    }
#pragma unroll
    for (int o = 16; o; o >>= 1) ss += __shfl_xor_sync(0xffffffffu, ss, o);
    __shared__ float red[8];
    if ((tid & 31) == 0) red[tid >> 5] = ss;
    __syncthreads();
    float tot = red[0] + red[1] + red[2] + red[3] + red[4] + red[5] + red[6] + red[7];
    float scale = rsqrtf(tot * (1.0f / 2048.0f) + 1e-5f);
#pragma unroll
    for (int i = 0; i < 8; i++) {
        int c = tid + i * 256;
        g_nrm[(size_t)row * D_INNER + c] = v[i] * scale * nw[c];
    }
}

// =====================================================================
extern "C" void kernel_launch(void* const* d_in, const int* in_sizes, int n_in,
                              void* d_out, int out_size)
{
    const float* x          = (const float*)d_in[0];
    const float* in_proj_w  = (const float*)d_in[1];
    const float* conv_w     = (const float*)d_in[2];
    const float* conv_b     = (const float*)d_in[3];
    const float* dt_bias    = (const float*)d_in[4];
    const float* A_log      = (const float*)d_in[5];
    const float* Dv         = (const float*)d_in[6];
    const float* norm_w     = (const float*)d_in[7];
    const float* out_proj_w = (const float*)d_in[8];
    float* out = (float*)d_out;

    float* zx  = nullptr;
    float* nrm = nullptr;
    cudaGetSymbolAddress((void**)&zx, g_zx);
    cudaGetSymbolAddress((void**)&nrm, g_nrm);

    // 1) in_proj: zx[4096,4384] = x @ in_proj_w^T
    gemm_tf32_split<<<dim3((D_IN_PROJ + BNT - 1) / BNT, BL / BMT), 256>>>(
        x, in_proj_w, zx, nullptr, BL, D_IN_PROJ, D_MODEL);

    // 2) causal conv + silu over xBC columns
    conv_silu_kernel<<<dim3(CONV_DIM / 256, BL), 256>>>(conv_w, conv_b);

    // 3) dt / dA preprocessing
    dt_kernel<<<(BL * NHEADS) / 256, 256>>>(dt_bias, A_log);

    // 4) sequential selective scan (+ D * x skip)
    scan_kernel<<<BATCH * NHEADS, 256>>>(Dv);

    // 5) gate with silu(z) + RMSNorm
    gatenorm_kernel<<<BL, 256>>>(norm_w);

    // 6) out_proj + residual: out = x + nrm @ out_proj_w^T
    gemm_tf32_split<<<dim3(D_MODEL / BNT, BL / BMT), 256>>>(
        nrm, out_proj_w, out, x, BL, D_MODEL, D_INNER);
}